// round 7
// baseline (speedup 1.0000x reference)
#include <cuda_runtime.h>

typedef unsigned long long ull;

constexpr int N = 1024, T = 512, B = 128, NI = 6, NO = 2;
constexpr float ALPHA = 0.1f, GAMMA = 0.1f;
constexpr float NOISE_SCALE = 0.13416407864998738f;   // sqrt(2/0.1)*0.03

constexpr int NBLK = 128;     // 64 row-tiles x 2 col-tiles, all co-resident
constexpr int NTHR = 256;
constexpr int RPB  = 16;      // rows per block
constexpr int CPB  = 64;      // batch cols per block
constexpr int KSPLIT = 8;     // one warp per k-range
constexpr int KRANGE = N / KSPLIT;     // 128
constexpr int SLABK  = 16;             // k rows per staged slab
constexpr int NSLAB  = KRANGE / SLABK; // 8

constexpr size_t W_BYTES     = (size_t)RPB * N * sizeof(ull);            // 128 KB
constexpr size_t STAGE_BYTES = (size_t)KSPLIT * 2 * SLABK * CPB * 4;     // 64 KB
constexpr size_t RED_BYTES   = (size_t)NTHR * 16 * sizeof(ull);          // 32 KB
constexpr size_t SMEM_TOTAL  = W_BYTES + STAGE_BYTES + RED_BYTES;        // 224 KB

__device__ float g_states[(size_t)T * N * B];   // 256 MB scratch
__device__ unsigned g_flag[16];                 // [colTile*8 + kGroup], monotonic per launch
__device__ unsigned g_count;
__device__ volatile unsigned g_gen;

__device__ __forceinline__ ull pack2(float x) {
    ull r; asm("mov.b64 %0, {%1, %1};" : "=l"(r) : "f"(x)); return r;
}
__device__ __forceinline__ float2 unpack2(ull v) {
    float2 r; asm("mov.b64 {%0, %1}, %2;" : "=f"(r.x), "=f"(r.y) : "l"(v)); return r;
}
__device__ __forceinline__ void ffma2(ull &acc, ull a, ull b) {
    asm("fma.rn.f32x2 %0, %1, %2, %0;" : "+l"(acc) : "l"(a), "l"(b));
}
__device__ __forceinline__ void cp_async16(unsigned dst, const void* src) {
    asm volatile("cp.async.cg.shared.global [%0], [%1], 16;" :: "r"(dst), "l"(src));
}
__device__ __forceinline__ void cp_commit() {
    asm volatile("cp.async.commit_group;");
}
template<int n> __device__ __forceinline__ void cp_wait() {
    asm volatile("cp.async.wait_group %0;" :: "n"(n));
}
__device__ __forceinline__ unsigned ld_acquire(const unsigned* p) {
    unsigned v;
    asm volatile("ld.acquire.gpu.global.u32 %0, [%1];" : "=r"(v) : "l"(p));
    return v;
}

// Final (once-per-launch) full grid barrier for flag reset.
__device__ __forceinline__ void grid_sync_final() {
    __syncthreads();
    if (threadIdx.x == 0) {
        unsigned gen = g_gen;
        __threadfence();
        if (atomicAdd(&g_count, 1u) == NBLK - 1) {
            g_count = 0;
            __threadfence();
            atomicAdd((unsigned*)&g_gen, 1u);
        } else {
            while (g_gen == gen) { __nanosleep(64); }
        }
        __threadfence();
    }
    __syncthreads();
}

__global__ void __launch_bounds__(NTHR, 1)
rnn_persistent_kernel(const float* __restrict__ u,
                      const float* __restrict__ rec_noise,
                      const float* __restrict__ inp_noise,
                      const float* __restrict__ W_rec,
                      const float* __restrict__ W_inp,
                      const float* __restrict__ y_init)
{
    extern __shared__ char smraw[];
    ull*   Wsh   = (ull*)smraw;                                 // [RPB][N] lane-dup
    float* Stage = (float*)(smraw + W_BYTES);                   // [KSPLIT][2][SLABK][CPB]
    ull*   Red   = (ull*)(smraw + W_BYTES + STAGE_BYTES);       // [NTHR][16] partials

    const int tid = threadIdx.x;
    const int w   = tid >> 5;          // warp = k-range owner
    const int l   = tid & 31;
    const int rg  = l >> 4;            // row-group: rows rg*8 .. +8 (local)
    const int cgr = l & 15;            // col-group: cols cgr*4 .. +3 (local)

    const int rowTile = blockIdx.x >> 1;
    const int colTile = blockIdx.x & 1;
    const int r0 = rowTile * RPB;
    const int c0 = colTile * CPB;

    // epilogue mapping (2 rows x 2 cols per thread)
    const int erp = tid >> 5;
    const int ep  = tid & 31;
    const int lra = erp * 2, lrb = lra + 1;
    const int ra  = r0 + lra, rb = r0 + lrb;
    const int ec  = c0 + ep * 2;

    unsigned* my_flag     = &g_flag[colTile * 8 + w];    // consumer side
    unsigned* arrive_flag = &g_flag[colTile * 8 + (rowTile >> 3)];

    // one-time: W_rec rows into smem, lane-duplicated
    for (int idx = tid; idx < RPB * N; idx += NTHR) {
        int r = idx >> 10;
        int k = idx & (N - 1);
        Wsh[idx] = pack2(W_rec[(size_t)(r0 + r) * N + k]);
    }

    float wia[NI], wib[NI];
#pragma unroll
    for (int i = 0; i < NI; i++) {
        wia[i] = W_inp[ra * NI + i];
        wib[i] = W_inp[rb * NI + i];
    }

    // states[0] = broadcast(y_init); carry own state in registers
    float2 soa, sob;
    {
        float ya = y_init[ra], yb = y_init[rb];
        soa = make_float2(ya, ya);
        sob = make_float2(yb, yb);
        *(float2*)&g_states[(size_t)ra * B + ec] = soa;
        *(float2*)&g_states[(size_t)rb * B + ec] = sob;
    }
    __syncthreads();
    if (tid == 0) { __threadfence(); atomicAdd(arrive_flag, 1u); }   // s0 ready

    const unsigned stage_base =
        (unsigned)__cvta_generic_to_shared(Stage) + (unsigned)(w * 2 * SLABK * CPB * 4);

    for (int t = 0; t < T - 1; t++) {
        const float* Sold = g_states + (size_t)t * (N * B);
        float*       Snew = g_states + (size_t)(t + 1) * (N * B);

        // prefetch epilogue operands (fly during flag wait + slab compute)
        float2 uu[NI], nn[NI];
#pragma unroll
        for (int i = 0; i < NI; i++) {
            const size_t off = (size_t)i * T * B + (size_t)t * B + ec;
            uu[i] = *(const float2*)&u[off];
            nn[i] = *(const float2*)&inp_noise[off];
        }
        float2 rna = *(const float2*)&rec_noise[(size_t)ra * T * B + (size_t)t * B + ec];
        float2 rnb = *(const float2*)&rec_noise[(size_t)rb * T * B + (size_t)t * B + ec];

        // wait for my k-range producers (8 blocks) to publish step-t state
        if (l == 0) {
            const unsigned need = 8u * (unsigned)(t + 1);
            if (ld_acquire(my_flag) < need) {
                while (ld_acquire(my_flag) < need) { __nanosleep(32); }
            }
        }
        __syncwarp();

        auto issue = [&](int s) {
            const int k0 = w * KRANGE + s * SLABK;
            const unsigned dst = stage_base + (unsigned)((s & 1) * (SLABK * CPB * 4));
            const float* src0 = Sold + (size_t)k0 * B + c0;
#pragma unroll
            for (int j = 0; j < 8; j++) {
                int f  = j * 32 + l;
                int kk = f >> 4;
                int cc = f & 15;
                cp_async16(dst + (unsigned)f * 16, src0 + (size_t)kk * B + cc * 4);
            }
            cp_commit();
        };

        issue(0);
        issue(1);

        ull acc[8][2];
#pragma unroll
        for (int rr = 0; rr < 8; rr++) { acc[rr][0] = 0ull; acc[rr][1] = 0ull; }

        for (int s = 0; s < NSLAB; s++) {
            if (s < NSLAB - 1) cp_wait<1>(); else cp_wait<0>();
            __syncwarp();

            const float* Sp = Stage + (w * 2 + (s & 1)) * (SLABK * CPB) + cgr * 4;
            const int kg0 = w * KRANGE + s * SLABK;

#pragma unroll
            for (int kk = 0; kk < SLABK; kk += 2) {
                ulonglong2 sv0 = *(const ulonglong2*)(Sp + (kk + 0) * CPB);
                ulonglong2 sv1 = *(const ulonglong2*)(Sp + (kk + 1) * CPB);
#pragma unroll
                for (int rr = 0; rr < 8; rr++) {
                    ulonglong2 wv = *(const ulonglong2*)&Wsh[(size_t)(rg * 8 + rr) * N + kg0 + kk];
                    ffma2(acc[rr][0], wv.x, sv0.x);
                    ffma2(acc[rr][1], wv.x, sv0.y);
                    ffma2(acc[rr][0], wv.y, sv1.x);
                    ffma2(acc[rr][1], wv.y, sv1.y);
                }
            }

            if (s + 2 < NSLAB) { __syncwarp(); issue(s + 2); }
        }

        // input projection from prefetched operands (uses registers only)
        float2 p0 = make_float2(0.f, 0.f), p1 = make_float2(0.f, 0.f);
#pragma unroll
        for (int i = 0; i < NI; i++) {
            float xx = fmaf(NOISE_SCALE, nn[i].x, uu[i].x);
            float xy = fmaf(NOISE_SCALE, nn[i].y, uu[i].y);
            p0.x = fmaf(wia[i], xx, p0.x);  p0.y = fmaf(wia[i], xy, p0.y);
            p1.x = fmaf(wib[i], xx, p1.x);  p1.y = fmaf(wib[i], xy, p1.y);
        }

        // cross-warp k-reduction through dedicated smem region
        __syncthreads();
        {
            ulonglong2* dst = (ulonglong2*)&Red[(size_t)(w * 32 + l) * 16];
#pragma unroll
            for (int rr = 0; rr < 8; rr++) {
                ulonglong2 v; v.x = acc[rr][0]; v.y = acc[rr][1];
                dst[rr] = v;
            }
        }
        __syncthreads();

        float2 h0 = p0, h1 = p1;
        {
            const int lane_a = (lra >> 3) * 16 + (ep >> 1);
            const int lane_b = (lrb >> 3) * 16 + (ep >> 1);
            const int ia = (lra & 7) * 2 + (ep & 1);
            const int ib = (lrb & 7) * 2 + (ep & 1);
#pragma unroll
            for (int wj = 0; wj < KSPLIT; wj++) {
                float2 fa = unpack2(Red[(size_t)(wj * 32 + lane_a) * 16 + ia]);
                float2 fb = unpack2(Red[(size_t)(wj * 32 + lane_b) * 16 + ib]);
                h0.x += fa.x; h0.y += fa.y;
                h1.x += fb.x; h1.y += fb.y;
            }
        }

        // pointwise Euler update (state carried in registers)
        {
            float hx = fmaxf(h0.x, 0.0f), hy = fmaxf(h0.y, 0.0f);
            float nx = soa.x + ALPHA * (-soa.x + hx + NOISE_SCALE * rna.x - GAMMA * soa.x * soa.x * soa.x);
            float ny = soa.y + ALPHA * (-soa.y + hy + NOISE_SCALE * rna.y - GAMMA * soa.y * soa.y * soa.y);
            soa = make_float2(nx, ny);
            *(float2*)&Snew[(size_t)ra * B + ec] = soa;
        }
        {
            float hx = fmaxf(h1.x, 0.0f), hy = fmaxf(h1.y, 0.0f);
            float nx = sob.x + ALPHA * (-sob.x + hx + NOISE_SCALE * rnb.x - GAMMA * sob.x * sob.x * sob.x);
            float ny = sob.y + ALPHA * (-sob.y + hy + NOISE_SCALE * rnb.y - GAMMA * sob.y * sob.y * sob.y);
            sob = make_float2(nx, ny);
            *(float2*)&Snew[(size_t)rb * B + ec] = sob;
        }

        __syncthreads();   // all Snew stores done before publish
        if (tid == 0) { __threadfence(); atomicAdd(arrive_flag, 1u); }
    }

    // reset flags for graph replay (behind one full barrier)
    grid_sync_final();
    if (blockIdx.x == 0 && tid < 16) g_flag[tid] = 0;
}

// outputs[o, t, c] = sum_r W_out[o, r] * states[t, r, c]
__global__ void __launch_bounds__(256)
readout_kernel(const float* __restrict__ W_out, float* __restrict__ out)
{
    __shared__ float wsh[NO * N];
    __shared__ float part[2][2][B];
    const int t = blockIdx.x;
    for (int i = threadIdx.x; i < NO * N; i += 256) wsh[i] = W_out[i];
    __syncthreads();

    const int half = threadIdx.x >> 7;
    const int cidx = threadIdx.x & 127;
    const float* S = g_states + (size_t)t * (N * B) + (size_t)half * (N / 2) * B;
    const float* w0 = wsh + half * (N / 2);
    float a0 = 0.0f, a1 = 0.0f;
#pragma unroll 8
    for (int r = 0; r < N / 2; r++) {
        float s = S[r * B + cidx];
        a0 = fmaf(w0[r], s, a0);
        a1 = fmaf(w0[N + r], s, a1);
    }
    part[half][0][cidx] = a0;
    part[half][1][cidx] = a1;
    __syncthreads();
    if (half == 0) {
        out[(size_t)t * B + cidx] = part[0][0][cidx] + part[1][0][cidx];
        out[(size_t)T * B + (size_t)t * B + cidx] = part[0][1][cidx] + part[1][1][cidx];
    }
}

extern "C" void kernel_launch(void* const* d_in, const int* in_sizes, int n_in,
                              void* d_out, int out_size)
{
    const float* u         = (const float*)d_in[0];
    const float* rec_noise = (const float*)d_in[1];
    const float* inp_noise = (const float*)d_in[2];
    const float* W_rec     = (const float*)d_in[3];
    const float* W_inp     = (const float*)d_in[4];
    const float* W_out     = (const float*)d_in[5];
    const float* y_init    = (const float*)d_in[6];
    float* out = (float*)d_out;

    cudaFuncSetAttribute(rnn_persistent_kernel,
                         cudaFuncAttributeMaxDynamicSharedMemorySize, (int)SMEM_TOTAL);

    rnn_persistent_kernel<<<NBLK, NTHR, SMEM_TOTAL>>>(u, rec_noise, inp_noise,
                                                      W_rec, W_inp, y_init);
    readout_kernel<<<T, 256>>>(W_out, out);
}

// round 8
// speedup vs baseline: 1.7135x; 1.7135x over previous
#include <cuda_runtime.h>

typedef unsigned long long ull;

constexpr int N = 1024, T = 512, B = 128, NI = 6, NO = 2;
constexpr float ALPHA = 0.1f, GAMMA = 0.1f;
constexpr float NOISE_SCALE = 0.13416407864998738f;   // sqrt(2/0.1)*0.03

constexpr int NBLK = 128;     // 64 row-tiles x 2 col-tiles, all co-resident
constexpr int NTHR = 256;
constexpr int RPB  = 16;      // rows per block
constexpr int CPB  = 64;      // batch cols per block
constexpr int KSPLIT = 8;     // one warp per k-range
constexpr int KRANGE = N / KSPLIT;     // 128
constexpr int SLABK  = 16;             // k rows per staged slab
constexpr int NSLAB  = KRANGE / SLABK; // 8

constexpr size_t W_BYTES     = (size_t)RPB * N * sizeof(ull);            // 128 KB
constexpr size_t STAGE_BYTES = (size_t)KSPLIT * 2 * SLABK * CPB * 4;     // 64 KB
constexpr size_t RED_BYTES   = (size_t)NTHR * 16 * sizeof(ull);          // 32 KB
constexpr size_t SMEM_TOTAL  = W_BYTES + STAGE_BYTES + RED_BYTES;        // 224 KB

__device__ float g_states[(size_t)T * N * B];   // 256 MB scratch
__device__ unsigned g_count;
__device__ volatile unsigned g_gen;

__device__ __forceinline__ ull pack2(float x) {
    ull r; asm("mov.b64 %0, {%1, %1};" : "=l"(r) : "f"(x)); return r;
}
__device__ __forceinline__ float2 unpack2(ull v) {
    float2 r; asm("mov.b64 {%0, %1}, %2;" : "=f"(r.x), "=f"(r.y) : "l"(v)); return r;
}
__device__ __forceinline__ void ffma2(ull &acc, ull a, ull b) {
    asm("fma.rn.f32x2 %0, %1, %2, %0;" : "+l"(acc) : "l"(a), "l"(b));
}
__device__ __forceinline__ void cp_async16(unsigned dst, const void* src) {
    asm volatile("cp.async.cg.shared.global [%0], [%1], 16;" :: "r"(dst), "l"(src));
}
__device__ __forceinline__ void cp_commit() {
    asm volatile("cp.async.commit_group;");
}
template<int n> __device__ __forceinline__ void cp_wait() {
    asm volatile("cp.async.wait_group %0;" :: "n"(n));
}

// Sense-reversing grid barrier (128 blocks, 1/SM guaranteed by 224KB smem)
__device__ __forceinline__ void grid_sync() {
    __syncthreads();
    if (threadIdx.x == 0) {
        unsigned gen = g_gen;
        __threadfence();
        if (atomicAdd(&g_count, 1u) == NBLK - 1) {
            g_count = 0;
            __threadfence();
            atomicAdd((unsigned*)&g_gen, 1u);
        } else {
            while (g_gen == gen) { __nanosleep(32); }
        }
        __threadfence();
    }
    __syncthreads();
}

__global__ void __launch_bounds__(NTHR, 1)
rnn_persistent_kernel(const float* __restrict__ u,
                      const float* __restrict__ rec_noise,
                      const float* __restrict__ inp_noise,
                      const float* __restrict__ W_rec,
                      const float* __restrict__ W_inp,
                      const float* __restrict__ y_init)
{
    extern __shared__ char smraw[];
    ull*   Wsh   = (ull*)smraw;                                 // [RPB][N] lane-dup
    float* Stage = (float*)(smraw + W_BYTES);                   // [KSPLIT][2][SLABK][CPB]
    ull*   Red   = (ull*)(smraw + W_BYTES + STAGE_BYTES);       // [NTHR][16], swizzled

    const int tid = threadIdx.x;
    const int w   = tid >> 5;          // warp = k-range owner
    const int l   = tid & 31;
    const int rg  = l >> 4;            // row-group: rows rg*8 .. +8 (local)
    const int cgr = l & 15;            // col-group: cols cgr*4 .. +3 (local)

    const int rowTile = blockIdx.x >> 1;
    const int colTile = blockIdx.x & 1;
    const int r0 = rowTile * RPB;
    const int c0 = colTile * CPB;

    // epilogue mapping (2 rows x 2 cols per thread)
    const int erp = tid >> 5;
    const int ep  = tid & 31;
    const int lra = erp * 2, lrb = lra + 1;
    const int ra  = r0 + lra, rb = r0 + lrb;
    const int ec  = c0 + ep * 2;

    // one-time: W_rec rows into smem, lane-duplicated
    for (int idx = tid; idx < RPB * N; idx += NTHR) {
        int r = idx >> 10;
        int k = idx & (N - 1);
        Wsh[idx] = pack2(W_rec[(size_t)(r0 + r) * N + k]);
    }

    float wia[NI], wib[NI];
#pragma unroll
    for (int i = 0; i < NI; i++) {
        wia[i] = W_inp[ra * NI + i];
        wib[i] = W_inp[rb * NI + i];
    }

    // states[0] = broadcast(y_init); carry own state in registers
    float2 soa, sob;
    {
        float ya = y_init[ra], yb = y_init[rb];
        soa = make_float2(ya, ya);
        sob = make_float2(yb, yb);
        *(float2*)&g_states[(size_t)ra * B + ec] = soa;
        *(float2*)&g_states[(size_t)rb * B + ec] = sob;
    }
    grid_sync();

    const unsigned stage_base =
        (unsigned)__cvta_generic_to_shared(Stage) + (unsigned)(w * 2 * SLABK * CPB * 4);

    // reduction swizzle constants
    ull* red_dst = &Red[(size_t)(w * 32 + l) * 16];
    const int rot_st = l & 15;
    const int lane_a = (lra >> 3) * 16 + (ep >> 1);
    const int lane_b = (lrb >> 3) * 16 + (ep >> 1);
    const int pa = (((lra & 7) * 2 + (ep & 1)) + (lane_a & 15)) & 15;
    const int pb = (((lrb & 7) * 2 + (ep & 1)) + (lane_b & 15)) & 15;

    for (int t = 0; t < T - 1; t++) {
        const float* Sold = g_states + (size_t)t * (N * B);
        float*       Snew = g_states + (size_t)(t + 1) * (N * B);

        // early prefetch of the DRAM-streamed operand (4 regs only)
        float2 rna = *(const float2*)&rec_noise[(size_t)ra * T * B + (size_t)t * B + ec];
        float2 rnb = *(const float2*)&rec_noise[(size_t)rb * T * B + (size_t)t * B + ec];

        auto issue = [&](int s) {
            const int k0 = w * KRANGE + s * SLABK;
            const unsigned dst = stage_base + (unsigned)((s & 1) * (SLABK * CPB * 4));
            const float* src0 = Sold + (size_t)k0 * B + c0;
#pragma unroll
            for (int j = 0; j < 8; j++) {
                int f  = j * 32 + l;
                int kk = f >> 4;
                int cc = f & 15;
                cp_async16(dst + (unsigned)f * 16, src0 + (size_t)kk * B + cc * 4);
            }
            cp_commit();
        };

        issue(0);
        issue(1);

        ull acc[8][2];
#pragma unroll
        for (int rr = 0; rr < 8; rr++) { acc[rr][0] = 0ull; acc[rr][1] = 0ull; }

        for (int s = 0; s < NSLAB; s++) {
            if (s < NSLAB - 1) cp_wait<1>(); else cp_wait<0>();
            __syncwarp();

            const float* Sp = Stage + (w * 2 + (s & 1)) * (SLABK * CPB) + cgr * 4;
            const int kg0 = w * KRANGE + s * SLABK;

#pragma unroll
            for (int kk = 0; kk < SLABK; kk += 2) {
                ulonglong2 sv0 = *(const ulonglong2*)(Sp + (kk + 0) * CPB);
                ulonglong2 sv1 = *(const ulonglong2*)(Sp + (kk + 1) * CPB);
#pragma unroll
                for (int rr = 0; rr < 8; rr++) {
                    ulonglong2 wv = *(const ulonglong2*)&Wsh[(size_t)(rg * 8 + rr) * N + kg0 + kk];
                    ffma2(acc[rr][0], wv.x, sv0.x);
                    ffma2(acc[rr][1], wv.x, sv0.y);
                    ffma2(acc[rr][0], wv.y, sv1.x);
                    ffma2(acc[rr][1], wv.y, sv1.y);
                }
            }

            if (s + 2 < NSLAB) { __syncwarp(); issue(s + 2); }
        }

        // prefetch L2-resident epilogue operands (latency hides under sync+reduce)
        float2 uu[NI], nn[NI];
#pragma unroll
        for (int i = 0; i < NI; i++) {
            const size_t off = (size_t)i * T * B + (size_t)t * B + ec;
            uu[i] = *(const float2*)&u[off];
            nn[i] = *(const float2*)&inp_noise[off];
        }

        // store partials, swizzled: element i lives at (i + row%16) % 16
#pragma unroll
        for (int rr = 0; rr < 8; rr++) {
            red_dst[(2 * rr     + rot_st) & 15] = acc[rr][0];
            red_dst[(2 * rr + 1 + rot_st) & 15] = acc[rr][1];
        }
        __syncthreads();

        // input projection
        float2 h0 = make_float2(0.f, 0.f), h1 = make_float2(0.f, 0.f);
#pragma unroll
        for (int i = 0; i < NI; i++) {
            float xx = fmaf(NOISE_SCALE, nn[i].x, uu[i].x);
            float xy = fmaf(NOISE_SCALE, nn[i].y, uu[i].y);
            h0.x = fmaf(wia[i], xx, h0.x);  h0.y = fmaf(wia[i], xy, h0.y);
            h1.x = fmaf(wib[i], xx, h1.x);  h1.y = fmaf(wib[i], xy, h1.y);
        }

        // sum 8 k-partials (swizzled reads, ~2-phase)
#pragma unroll
        for (int wj = 0; wj < KSPLIT; wj++) {
            float2 fa = unpack2(Red[(size_t)(wj * 32 + lane_a) * 16 + pa]);
            float2 fb = unpack2(Red[(size_t)(wj * 32 + lane_b) * 16 + pb]);
            h0.x += fa.x; h0.y += fa.y;
            h1.x += fb.x; h1.y += fb.y;
        }

        // pointwise Euler update (state carried in registers)
        {
            float hx = fmaxf(h0.x, 0.0f), hy = fmaxf(h0.y, 0.0f);
            float nx = soa.x + ALPHA * (-soa.x + hx + NOISE_SCALE * rna.x - GAMMA * soa.x * soa.x * soa.x);
            float ny = soa.y + ALPHA * (-soa.y + hy + NOISE_SCALE * rna.y - GAMMA * soa.y * soa.y * soa.y);
            soa = make_float2(nx, ny);
            *(float2*)&Snew[(size_t)ra * B + ec] = soa;
        }
        {
            float hx = fmaxf(h1.x, 0.0f), hy = fmaxf(h1.y, 0.0f);
            float nx = sob.x + ALPHA * (-sob.x + hx + NOISE_SCALE * rnb.x - GAMMA * sob.x * sob.x * sob.x);
            float ny = sob.y + ALPHA * (-sob.y + hy + NOISE_SCALE * rnb.y - GAMMA * sob.y * sob.y * sob.y);
            sob = make_float2(nx, ny);
            *(float2*)&Snew[(size_t)rb * B + ec] = sob;
        }

        grid_sync();
    }
}

// outputs[o, t, c] = sum_r W_out[o, r] * states[t, r, c]
__global__ void __launch_bounds__(256)
readout_kernel(const float* __restrict__ W_out, float* __restrict__ out)
{
    __shared__ float wsh[NO * N];
    __shared__ float part[2][2][B];
    const int t = blockIdx.x;
    for (int i = threadIdx.x; i < NO * N; i += 256) wsh[i] = W_out[i];
    __syncthreads();

    const int half = threadIdx.x >> 7;
    const int cidx = threadIdx.x & 127;
    const float* S = g_states + (size_t)t * (N * B) + (size_t)half * (N / 2) * B;
    const float* w0 = wsh + half * (N / 2);
    float a0 = 0.0f, a1 = 0.0f;
#pragma unroll 8
    for (int r = 0; r < N / 2; r++) {
        float s = S[r * B + cidx];
        a0 = fmaf(w0[r], s, a0);
        a1 = fmaf(w0[N + r], s, a1);
    }
    part[half][0][cidx] = a0;
    part[half][1][cidx] = a1;
    __syncthreads();
    if (half == 0) {
        out[(size_t)t * B + cidx] = part[0][0][cidx] + part[1][0][cidx];
        out[(size_t)T * B + (size_t)t * B + cidx] = part[0][1][cidx] + part[1][1][cidx];
    }
}

extern "C" void kernel_launch(void* const* d_in, const int* in_sizes, int n_in,
                              void* d_out, int out_size)
{
    const float* u         = (const float*)d_in[0];
    const float* rec_noise = (const float*)d_in[1];
    const float* inp_noise = (const float*)d_in[2];
    const float* W_rec     = (const float*)d_in[3];
    const float* W_inp     = (const float*)d_in[4];
    const float* W_out     = (const float*)d_in[5];
    const float* y_init    = (const float*)d_in[6];
    float* out = (float*)d_out;

    cudaFuncSetAttribute(rnn_persistent_kernel,
                         cudaFuncAttributeMaxDynamicSharedMemorySize, (int)SMEM_TOTAL);

    rnn_persistent_kernel<<<NBLK, NTHR, SMEM_TOTAL>>>(u, rec_noise, inp_noise,
                                                      W_rec, W_inp, y_init);
    readout_kernel<<<T, 256>>>(W_out, out);
}

// round 9
// speedup vs baseline: 1.8131x; 1.0581x over previous
#include <cuda_runtime.h>

typedef unsigned long long ull;

constexpr int N = 1024, T = 512, B = 128, NI = 6, NO = 2;
constexpr float ALPHA = 0.1f, GAMMA = 0.1f;
constexpr float NOISE_SCALE = 0.13416407864998738f;   // sqrt(2/0.1)*0.03

constexpr int NBLK = 128;     // 64 row-tiles x 2 col-tiles, all co-resident
constexpr int NTHR = 256;
constexpr int RPB  = 16;      // rows per block
constexpr int CPB  = 64;      // batch cols per block
constexpr int KSPLIT = 8;     // one warp per k-range
constexpr int KRANGE = N / KSPLIT;     // 128
constexpr int SLABK  = 16;             // k rows per staged slab
constexpr int NSLAB  = KRANGE / SLABK; // 8

constexpr size_t W_BYTES     = (size_t)RPB * N * sizeof(ull);            // 128 KB
constexpr size_t STAGE_BYTES = (size_t)KSPLIT * 2 * SLABK * CPB * 4;     // 64 KB
constexpr size_t RED_BYTES   = (size_t)NTHR * 16 * sizeof(ull);          // 32 KB
constexpr size_t SMEM_TOTAL  = W_BYTES + STAGE_BYTES + RED_BYTES;        // 224 KB

__device__ float g_states[(size_t)T * N * B];   // 256 MB scratch
__device__ unsigned g_count;
__device__ unsigned g_gen;

__device__ __forceinline__ ull pack2(float x) {
    ull r; asm("mov.b64 %0, {%1, %1};" : "=l"(r) : "f"(x)); return r;
}
__device__ __forceinline__ float2 unpack2(ull v) {
    float2 r; asm("mov.b64 {%0, %1}, %2;" : "=f"(r.x), "=f"(r.y) : "l"(v)); return r;
}
__device__ __forceinline__ void ffma2(ull &acc, ull a, ull b) {
    asm("fma.rn.f32x2 %0, %1, %2, %0;" : "+l"(acc) : "l"(a), "l"(b));
}
__device__ __forceinline__ void cp_async16(unsigned dst, const void* src) {
    asm volatile("cp.async.cg.shared.global [%0], [%1], 16;" :: "r"(dst), "l"(src));
}
__device__ __forceinline__ void cp_commit() {
    asm volatile("cp.async.commit_group;");
}
template<int n> __device__ __forceinline__ void cp_wait() {
    asm volatile("cp.async.wait_group %0;" :: "n"(n));
}
__device__ __forceinline__ unsigned ld_acquire(const unsigned* p) {
    unsigned v;
    asm volatile("ld.acquire.gpu.global.u32 %0, [%1];" : "=r"(v) : "l"(p));
    return v;
}
__device__ __forceinline__ unsigned ld_relaxed(const unsigned* p) {
    unsigned v;
    asm volatile("ld.relaxed.gpu.global.u32 %0, [%1];" : "=r"(v) : "l"(p));
    return v;
}
__device__ __forceinline__ void red_release_add(unsigned* p, unsigned v) {
    asm volatile("red.release.gpu.global.add.u32 [%0], %1;" :: "l"(p), "r"(v));
}

// Sense-reversing grid barrier. release-arrive + acquire-spin, no nanosleep.
__device__ __forceinline__ void grid_sync() {
    __syncthreads();
    if (threadIdx.x == 0) {
        unsigned gen = ld_relaxed(&g_gen);
        // release: orders this block's prior global stores before the arrival
        unsigned old = atomicAdd(&g_count, 1u);   // atom returns old; ordering via fence below
        __threadfence();                          // ensure stores visible (atomicAdd is relaxed)
        if (old == NBLK - 1) {
            g_count = 0;
            red_release_add(&g_gen, 1u);
        } else {
            while (ld_acquire(&g_gen) == gen) { }
        }
    }
    __syncthreads();
}

__global__ void __launch_bounds__(NTHR, 1)
rnn_persistent_kernel(const float* __restrict__ u,
                      const float* __restrict__ rec_noise,
                      const float* __restrict__ inp_noise,
                      const float* __restrict__ W_rec,
                      const float* __restrict__ W_inp,
                      const float* __restrict__ y_init)
{
    extern __shared__ char smraw[];
    ull*   Wsh   = (ull*)smraw;                                 // [RPB][N] lane-dup
    float* Stage = (float*)(smraw + W_BYTES);                   // [KSPLIT][2][SLABK][CPB]
    ull*   Red   = (ull*)(smraw + W_BYTES + STAGE_BYTES);       // [NTHR][16], swizzled

    const int tid = threadIdx.x;
    const int w   = tid >> 5;          // warp = k-range owner
    const int l   = tid & 31;
    const int rg  = l >> 4;            // row-group: rows rg*8 .. +8 (local)
    const int cgr = l & 15;            // col-group: cols cgr*4 .. +3 (local)

    const int rowTile = blockIdx.x >> 1;
    const int colTile = blockIdx.x & 1;
    const int r0 = rowTile * RPB;
    const int c0 = colTile * CPB;

    // epilogue mapping (2 rows x 2 cols per thread)
    const int erp = tid >> 5;
    const int ep  = tid & 31;
    const int lra = erp * 2, lrb = lra + 1;
    const int ra  = r0 + lra, rb = r0 + lrb;
    const int ec  = c0 + ep * 2;

    // one-time: W_rec rows into smem, lane-duplicated
    for (int idx = tid; idx < RPB * N; idx += NTHR) {
        int r = idx >> 10;
        int k = idx & (N - 1);
        Wsh[idx] = pack2(W_rec[(size_t)(r0 + r) * N + k]);
    }

    float wia[NI], wib[NI];
#pragma unroll
    for (int i = 0; i < NI; i++) {
        wia[i] = W_inp[ra * NI + i];
        wib[i] = W_inp[rb * NI + i];
    }

    // states[0] = broadcast(y_init); carry own state in registers
    float2 soa, sob;
    {
        float ya = y_init[ra], yb = y_init[rb];
        soa = make_float2(ya, ya);
        sob = make_float2(yb, yb);
        *(float2*)&g_states[(size_t)ra * B + ec] = soa;
        *(float2*)&g_states[(size_t)rb * B + ec] = sob;
    }
    grid_sync();

    const unsigned stage_base =
        (unsigned)__cvta_generic_to_shared(Stage) + (unsigned)(w * 2 * SLABK * CPB * 4);

    // reduction swizzle constants
    ull* red_dst = &Red[(size_t)(w * 32 + l) * 16];
    const int rot_st = l & 15;
    const int lane_a = (lra >> 3) * 16 + (ep >> 1);
    const int lane_b = (lrb >> 3) * 16 + (ep >> 1);
    const int pa = (((lra & 7) * 2 + (ep & 1)) + (lane_a & 15)) & 15;
    const int pb = (((lrb & 7) * 2 + (ep & 1)) + (lane_b & 15)) & 15;

    for (int t = 0; t < T - 1; t++) {
        const float* Sold = g_states + (size_t)t * (N * B);
        float*       Snew = g_states + (size_t)(t + 1) * (N * B);

        // prefetch ALL epilogue operands at step top (latency hidden under GEMM)
        float2 rna = *(const float2*)&rec_noise[(size_t)ra * T * B + (size_t)t * B + ec];
        float2 rnb = *(const float2*)&rec_noise[(size_t)rb * T * B + (size_t)t * B + ec];
        float2 uu[NI], nn[NI];
#pragma unroll
        for (int i = 0; i < NI; i++) {
            const size_t off = (size_t)i * T * B + (size_t)t * B + ec;
            uu[i] = *(const float2*)&u[off];
            nn[i] = *(const float2*)&inp_noise[off];
        }

        auto issue = [&](int s) {
            const int k0 = w * KRANGE + s * SLABK;
            const unsigned dst = stage_base + (unsigned)((s & 1) * (SLABK * CPB * 4));
            const float* src0 = Sold + (size_t)k0 * B + c0;
#pragma unroll
            for (int j = 0; j < 8; j++) {
                int f  = j * 32 + l;
                int kk = f >> 4;
                int cc = f & 15;
                cp_async16(dst + (unsigned)f * 16, src0 + (size_t)kk * B + cc * 4);
            }
            cp_commit();
        };

        issue(0);
        issue(1);

        // input projection here: fills the exposed first-slab L2 latency
        float2 p0 = make_float2(0.f, 0.f), p1 = make_float2(0.f, 0.f);
#pragma unroll
        for (int i = 0; i < NI; i++) {
            float xx = fmaf(NOISE_SCALE, nn[i].x, uu[i].x);
            float xy = fmaf(NOISE_SCALE, nn[i].y, uu[i].y);
            p0.x = fmaf(wia[i], xx, p0.x);  p0.y = fmaf(wia[i], xy, p0.y);
            p1.x = fmaf(wib[i], xx, p1.x);  p1.y = fmaf(wib[i], xy, p1.y);
        }

        ull acc[8][2];
#pragma unroll
        for (int rr = 0; rr < 8; rr++) { acc[rr][0] = 0ull; acc[rr][1] = 0ull; }

        for (int s = 0; s < NSLAB; s++) {
            if (s < NSLAB - 1) cp_wait<1>(); else cp_wait<0>();
            __syncwarp();

            const float* Sp = Stage + (w * 2 + (s & 1)) * (SLABK * CPB) + cgr * 4;
            const int kg0 = w * KRANGE + s * SLABK;

#pragma unroll
            for (int kk = 0; kk < SLABK; kk += 2) {
                ulonglong2 sv0 = *(const ulonglong2*)(Sp + (kk + 0) * CPB);
                ulonglong2 sv1 = *(const ulonglong2*)(Sp + (kk + 1) * CPB);
#pragma unroll
                for (int rr = 0; rr < 8; rr++) {
                    ulonglong2 wv = *(const ulonglong2*)&Wsh[(size_t)(rg * 8 + rr) * N + kg0 + kk];
                    ffma2(acc[rr][0], wv.x, sv0.x);
                    ffma2(acc[rr][1], wv.x, sv0.y);
                    ffma2(acc[rr][0], wv.y, sv1.x);
                    ffma2(acc[rr][1], wv.y, sv1.y);
                }
            }

            if (s + 2 < NSLAB) { __syncwarp(); issue(s + 2); }
        }

        // store partials, swizzled: element i lives at (i + row%16) % 16
#pragma unroll
        for (int rr = 0; rr < 8; rr++) {
            red_dst[(2 * rr     + rot_st) & 15] = acc[rr][0];
            red_dst[(2 * rr + 1 + rot_st) & 15] = acc[rr][1];
        }
        __syncthreads();

        // sum 8 k-partials (swizzled reads, ~2-phase)
        float2 h0 = p0, h1 = p1;
#pragma unroll
        for (int wj = 0; wj < KSPLIT; wj++) {
            float2 fa = unpack2(Red[(size_t)(wj * 32 + lane_a) * 16 + pa]);
            float2 fb = unpack2(Red[(size_t)(wj * 32 + lane_b) * 16 + pb]);
            h0.x += fa.x; h0.y += fa.y;
            h1.x += fb.x; h1.y += fb.y;
        }

        // pointwise Euler update (state carried in registers)
        {
            float hx = fmaxf(h0.x, 0.0f), hy = fmaxf(h0.y, 0.0f);
            float nx = soa.x + ALPHA * (-soa.x + hx + NOISE_SCALE * rna.x - GAMMA * soa.x * soa.x * soa.x);
            float ny = soa.y + ALPHA * (-soa.y + hy + NOISE_SCALE * rna.y - GAMMA * soa.y * soa.y * soa.y);
            soa = make_float2(nx, ny);
            *(float2*)&Snew[(size_t)ra * B + ec] = soa;
        }
        {
            float hx = fmaxf(h1.x, 0.0f), hy = fmaxf(h1.y, 0.0f);
            float nx = sob.x + ALPHA * (-sob.x + hx + NOISE_SCALE * rnb.x - GAMMA * sob.x * sob.x * sob.x);
            float ny = sob.y + ALPHA * (-sob.y + hy + NOISE_SCALE * rnb.y - GAMMA * sob.y * sob.y * sob.y);
            sob = make_float2(nx, ny);
            *(float2*)&Snew[(size_t)rb * B + ec] = sob;
        }

        grid_sync();
    }
}

// outputs[o, t, c] = sum_r W_out[o, r] * states[t, r, c]
__global__ void __launch_bounds__(256)
readout_kernel(const float* __restrict__ W_out, float* __restrict__ out)
{
    __shared__ float wsh[NO * N];
    __shared__ float part[2][2][B];
    const int t = blockIdx.x;
    for (int i = threadIdx.x; i < NO * N; i += 256) wsh[i] = W_out[i];
    __syncthreads();

    const int half = threadIdx.x >> 7;
    const int cidx = threadIdx.x & 127;
    const float* S = g_states + (size_t)t * (N * B) + (size_t)half * (N / 2) * B;
    const float* w0 = wsh + half * (N / 2);
    float a0 = 0.0f, a1 = 0.0f;
#pragma unroll 8
    for (int r = 0; r < N / 2; r++) {
        float s = S[r * B + cidx];
        a0 = fmaf(w0[r], s, a0);
        a1 = fmaf(w0[N + r], s, a1);
    }
    part[half][0][cidx] = a0;
    part[half][1][cidx] = a1;
    __syncthreads();
    if (half == 0) {
        out[(size_t)t * B + cidx] = part[0][0][cidx] + part[1][0][cidx];
        out[(size_t)T * B + (size_t)t * B + cidx] = part[0][1][cidx] + part[1][1][cidx];
    }
}

// trivial kernel to shift ncu's launch indexing so -s 5 lands on the persistent kernel
__global__ void pad_kernel() { }

extern "C" void kernel_launch(void* const* d_in, const int* in_sizes, int n_in,
                              void* d_out, int out_size)
{
    const float* u         = (const float*)d_in[0];
    const float* rec_noise = (const float*)d_in[1];
    const float* inp_noise = (const float*)d_in[2];
    const float* W_rec     = (const float*)d_in[3];
    const float* W_inp     = (const float*)d_in[4];
    const float* W_out     = (const float*)d_in[5];
    const float* y_init    = (const float*)d_in[6];
    float* out = (float*)d_out;

    cudaFuncSetAttribute(rnn_persistent_kernel,
                         cudaFuncAttributeMaxDynamicSharedMemorySize, (int)SMEM_TOTAL);

    pad_kernel<<<1, 32>>>();                 // launch sequence per call: D, P, R, D
    rnn_persistent_kernel<<<NBLK, NTHR, SMEM_TOTAL>>>(u, rec_noise, inp_noise,
                                                      W_rec, W_inp, y_init);
    readout_kernel<<<T, 256>>>(W_out, out);
    pad_kernel<<<1, 32>>>();
}